// round 2
// baseline (speedup 1.0000x reference)
#include <cuda_runtime.h>
#include <math.h>

// ---------------- problem constants ----------------
#define NF     128          // nfeats
#define NOUT   512          // 4*NF gate channels
#define BATCH  4
#define TT     8
#define HH     32
#define WW     32
#define HP     34           // padded spatial
#define NPIX   1024         // 32*32
#define M_TOTAL 4096        // BATCH*NPIX
#define CIN1   384          // 2*NF + NF (layer 1 input channels)
#define CIN23  256          // 2*NF     (layers 2/3)
#define K1     (CIN1 * 9)
#define K23    (CIN23 * 9)
#define PLANE  (HP * HP)    // 1156

// ---------------- persistent device scratch (no allocs allowed) ----------------
__device__ float g_ipad[BATCH * CIN1 * PLANE];   // padded packed input (max layer-1 size)
__device__ float g_z[M_TOTAL * NOUT];            // conv output (pre-gate)
__device__ float g_h1[BATCH * NF * NPIX];
__device__ float g_c1[BATCH * NF * NPIX];
__device__ float g_h2[BATCH * NF * NPIX];
__device__ float g_c2[BATCH * NF * NPIX];
__device__ float g_h3[BATCH * NF * NPIX];
__device__ float g_c3[BATCH * NF * NPIX];
__device__ float g_wt1[K1 * NOUT];               // transposed weights: Wt[(tap*Cin+ci)*512 + n]
__device__ float g_wt2[K23 * NOUT];
__device__ float g_wt3[K23 * NOUT];

// ---------------- utility kernels ----------------
__global__ void zero_kernel(float* __restrict__ p, int n) {
    int i = blockIdx.x * 256 + threadIdx.x;
    if (i < n) p[i] = 0.0f;
}

// W layout in: (512, Cin, 3, 3) row-major -> W[n*K + ci*9 + tap]
// out: Wt[(tap*Cin + ci)*512 + n]  (coalesced for GEMM B-tile loads)
__global__ void wtrans_kernel(const float* __restrict__ W, float* __restrict__ Wt, int Cin) {
    int K = Cin * 9;
    int idx = blockIdx.x * 256 + threadIdx.x;
    if (idx >= K * NOUT) return;
    int kp = idx >> 9;          // / 512
    int n  = idx & 511;
    int tap = kp / Cin;
    int ci  = kp - tap * Cin;
    Wt[idx] = W[n * K + ci * 9 + tap];
}

// Layer 1 pack: concat(x1[t], x2[t], h1) -> padded (B, 384, 34, 34)
__global__ void pack_l1_kernel(const float* __restrict__ x1, const float* __restrict__ x2,
                               int t) {
    int idx = blockIdx.x * 256 + threadIdx.x;   // over BATCH*CIN1*NPIX
    if (idx >= BATCH * CIN1 * NPIX) return;
    int pix = idx & 1023;
    int ci  = (idx >> 10) % CIN1;
    int b   = idx / (CIN1 * NPIX);
    float v;
    if (ci < 128)       v = x1[((b * TT + t) * NF + ci)       * NPIX + pix];
    else if (ci < 256)  v = x2[((b * TT + t) * NF + (ci-128)) * NPIX + pix];
    else                v = g_h1[(b * NF + (ci - 256)) * NPIX + pix];
    int y = pix >> 5, x = pix & 31;
    g_ipad[((b * CIN1 + ci) * HP + y + 1) * HP + x + 1] = v;
}

// Layers 2/3 pack: concat(h_below, h_self) -> padded (B, 256, 34, 34)
__global__ void pack_l23_kernel(const float* __restrict__ lo, const float* __restrict__ hi) {
    int idx = blockIdx.x * 256 + threadIdx.x;   // over BATCH*CIN23*NPIX
    if (idx >= BATCH * CIN23 * NPIX) return;
    int pix = idx & 1023;
    int ci  = (idx >> 10) % CIN23;
    int b   = idx / (CIN23 * NPIX);
    float v = (ci < 128) ? lo[(b * NF + ci) * NPIX + pix]
                         : hi[(b * NF + (ci - 128)) * NPIX + pix];
    int y = pix >> 5, x = pix & 31;
    g_ipad[((b * CIN23 + ci) * HP + y + 1) * HP + x + 1] = v;
}

// ---------------- implicit-GEMM conv: Z[m][n] = sum_k A[m][k] * Wt[k][n] ----------------
// M=4096, N=512, K=Cin*9. BM=128, BN=64, BK=8, 256 threads, 8x4 per-thread micro-tile.
__global__ void __launch_bounds__(256, 2)
conv_gemm_kernel(const float* __restrict__ Ipad, const float* __restrict__ Wt, int Cin) {
    __shared__ float As[8][128];
    __shared__ float Bs[8][64];

    const int lid = threadIdx.x;
    const int m0  = blockIdx.x * 128;      // 0..31 blocks (within one image: 1024 % 128 == 0)
    const int n0  = blockIdx.y * 64;       // 0..7 blocks

    const int b    = m0 >> 10;
    const int pix0 = m0 & 1023;

    // A-load coords (fixed per thread)
    const int mmA  = lid & 127;
    const int kk0  = lid >> 7;             // 0..1
    const int pixA = pix0 + mmA;
    const int yA   = pixA >> 5;
    const int xA   = pixA & 31;

    // B-load coords
    const int nnB  = lid & 63;
    const int kkB0 = lid >> 6;             // 0..3

    // compute coords
    const int tx = lid & 15;               // n dir (4 cols each)
    const int ty = lid >> 4;               // m dir (8 rows each)

    const float* ipb = Ipad + (size_t)b * Cin * PLANE;

    float acc[8][4];
#pragma unroll
    for (int i = 0; i < 8; ++i)
#pragma unroll
        for (int j = 0; j < 4; ++j) acc[i][j] = 0.0f;

#pragma unroll 1
    for (int tap = 0; tap < 9; ++tap) {
        const int kh = tap / 3;
        const int kw = tap - kh * 3;
        const int sp = (yA + kh) * HP + (xA + kw);        // A spatial offset for this tap
        const float* wrow = Wt + (size_t)tap * Cin * NOUT;

#pragma unroll 1
        for (int cb = 0; cb < Cin; cb += 8) {
            // load A tile: As[kk][mm]
            const float* ap = ipb + (size_t)cb * PLANE + sp;
#pragma unroll
            for (int it = 0; it < 4; ++it) {
                int kk = kk0 + it * 2;
                As[kk][mmA] = ap[kk * PLANE];
            }
            // load B tile: Bs[kk][nn]
            const float* bp = wrow + (size_t)cb * NOUT + n0 + nnB;
#pragma unroll
            for (int it = 0; it < 2; ++it) {
                int kk = kkB0 + it * 4;
                Bs[kk][nnB] = bp[kk * NOUT];
            }
            __syncthreads();

#pragma unroll
            for (int kk = 0; kk < 8; ++kk) {
                float4 a0 = *(const float4*)&As[kk][ty * 8];
                float4 a1 = *(const float4*)&As[kk][ty * 8 + 4];
                float4 bb = *(const float4*)&Bs[kk][tx * 4];
                float av[8] = {a0.x, a0.y, a0.z, a0.w, a1.x, a1.y, a1.z, a1.w};
                float bv[4] = {bb.x, bb.y, bb.z, bb.w};
#pragma unroll
                for (int i = 0; i < 8; ++i)
#pragma unroll
                    for (int j = 0; j < 4; ++j)
                        acc[i][j] += av[i] * bv[j];
            }
            __syncthreads();
        }
    }

    // epilogue: Z is [m][512]
#pragma unroll
    for (int i = 0; i < 8; ++i) {
        int m = m0 + ty * 8 + i;
        float4 v = make_float4(acc[i][0], acc[i][1], acc[i][2], acc[i][3]);
        *(float4*)&g_z[(size_t)m * NOUT + n0 + tx * 4] = v;
    }
}

// ---------------- pointwise LSTM gate update ----------------
__global__ void lstm_kernel(const float* __restrict__ bias,
                            float* __restrict__ c_st, float* __restrict__ h_st) {
    int idx = blockIdx.x * 256 + threadIdx.x;      // over BATCH*NF*NPIX = 524288
    if (idx >= BATCH * NF * NPIX) return;
    int cch = idx & 127;
    int m   = idx >> 7;
    int b   = m >> 10;
    int pix = m & 1023;

    const float* zr = g_z + (size_t)m * NOUT;
    float zi = zr[cch]        + bias[cch];
    float zf = zr[128 + cch]  + bias[128 + cch];
    float zo = zr[256 + cch]  + bias[256 + cch];
    float zg = zr[384 + cch]  + bias[384 + cch];

    float gi = 1.0f / (1.0f + expf(-zi));
    float gf = 1.0f / (1.0f + expf(-zf));
    float go = 1.0f / (1.0f + expf(-zo));
    float gg = tanhf(zg);

    int s = (b * NF + cch) * NPIX + pix;
    float cn = gf * c_st[s] + gi * gg;
    c_st[s] = cn;
    h_st[s] = go * tanhf(cn);
}

__global__ void copy_out_kernel(float* __restrict__ out) {
    int i = blockIdx.x * 256 + threadIdx.x;
    if (i < BATCH * NF * NPIX) out[i] = g_h3[i];
}

// ---------------- launch ----------------
extern "C" void kernel_launch(void* const* d_in, const int* in_sizes, int n_in,
                              void* d_out, int out_size) {
    const float* x1 = (const float*)d_in[0];
    const float* x2 = (const float*)d_in[1];
    const float* W1 = (const float*)d_in[2];
    const float* b1 = (const float*)d_in[3];
    const float* W2 = (const float*)d_in[4];
    const float* b2 = (const float*)d_in[5];
    const float* W3 = (const float*)d_in[6];
    const float* b3 = (const float*)d_in[7];
    float* out = (float*)d_out;

    float *p_ipad, *p_h1, *p_c1, *p_h2, *p_c2, *p_h3, *p_c3, *p_wt1, *p_wt2, *p_wt3;
    cudaGetSymbolAddress((void**)&p_ipad, g_ipad);
    cudaGetSymbolAddress((void**)&p_h1, g_h1);
    cudaGetSymbolAddress((void**)&p_c1, g_c1);
    cudaGetSymbolAddress((void**)&p_h2, g_h2);
    cudaGetSymbolAddress((void**)&p_c2, g_c2);
    cudaGetSymbolAddress((void**)&p_h3, g_h3);
    cudaGetSymbolAddress((void**)&p_c3, g_c3);
    cudaGetSymbolAddress((void**)&p_wt1, g_wt1);
    cudaGetSymbolAddress((void**)&p_wt2, g_wt2);
    cudaGetSymbolAddress((void**)&p_wt3, g_wt3);

    const int ST = BATCH * NF * NPIX;          // 524288
    const int IP = BATCH * CIN1 * PLANE;       // 1775616
    auto nb = [](int n) { return (n + 255) / 256; };

    // deterministic state reset every launch
    zero_kernel<<<nb(IP), 256>>>(p_ipad, IP);
    zero_kernel<<<nb(ST), 256>>>(p_h1, ST);
    zero_kernel<<<nb(ST), 256>>>(p_c1, ST);
    zero_kernel<<<nb(ST), 256>>>(p_h2, ST);
    zero_kernel<<<nb(ST), 256>>>(p_c2, ST);
    zero_kernel<<<nb(ST), 256>>>(p_h3, ST);
    zero_kernel<<<nb(ST), 256>>>(p_c3, ST);

    // weight transposes (cheap; L2-resident afterwards)
    wtrans_kernel<<<nb(K1 * NOUT), 256>>>(W1, p_wt1, CIN1);
    wtrans_kernel<<<nb(K23 * NOUT), 256>>>(W2, p_wt2, CIN23);
    wtrans_kernel<<<nb(K23 * NOUT), 256>>>(W3, p_wt3, CIN23);

    dim3 ggrid(32, 8);
    const int NP1  = BATCH * CIN1 * NPIX;      // 1572864
    const int NP23 = BATCH * CIN23 * NPIX;     // 1048576

    for (int t = 0; t < TT; ++t) {
        // layer 1
        pack_l1_kernel<<<nb(NP1), 256>>>(x1, x2, t);
        conv_gemm_kernel<<<ggrid, 256>>>(p_ipad, p_wt1, CIN1);
        lstm_kernel<<<nb(ST), 256>>>(b1, p_c1, p_h1);
        // layer 2
        pack_l23_kernel<<<nb(NP23), 256>>>(p_h1, p_h2);
        conv_gemm_kernel<<<ggrid, 256>>>(p_ipad, p_wt2, CIN23);
        lstm_kernel<<<nb(ST), 256>>>(b2, p_c2, p_h2);
        // layer 3
        pack_l23_kernel<<<nb(NP23), 256>>>(p_h2, p_h3);
        conv_gemm_kernel<<<ggrid, 256>>>(p_ipad, p_wt3, CIN23);
        lstm_kernel<<<nb(ST), 256>>>(b3, p_c3, p_h3);
    }

    copy_out_kernel<<<nb(ST), 256>>>(out);
}

// round 4
// speedup vs baseline: 1.8562x; 1.8562x over previous
#include <cuda_runtime.h>
#include <cstdint>
#include <math.h>

// ---------------- problem constants ----------------
#define NF     128
#define NOUT   512
#define BATCH  4
#define TT     8
#define HP     34
#define NPIX   1024
#define CIN1   384
#define CIN23  256
#define K1     (CIN1 * 9)     // 3456
#define K23    (CIN23 * 9)    // 2304
#define PLANE  (HP * HP)      // 1156

// GEMM tiling: CTA 128x128x32, 8 warps (2 m x 4 n), warp tile 64x32, mma m16n8k8
#define BM 128
#define BN 128
#define BK 32
#define SMEM_DYN 65536

// ---------------- persistent device scratch ----------------
__device__ float g_ipad[BATCH * CIN1 * PLANE];
__device__ float g_h1[BATCH * NF * NPIX];
__device__ float g_c1[BATCH * NF * NPIX];
__device__ float g_h2[BATCH * NF * NPIX];
__device__ float g_c2[BATCH * NF * NPIX];
__device__ float g_h3[BATCH * NF * NPIX];
__device__ float g_c3[BATCH * NF * NPIX];
__device__ float g_wf1[K1 * NOUT];     // fragment-ordered weights
__device__ float g_wf2[K23 * NOUT];
__device__ float g_wf3[K23 * NOUT];
__device__ float g_bp1[NOUT];          // bias reordered to n' = ch*4+gate
__device__ float g_bp2[NOUT];
__device__ float g_bp3[NOUT];

__device__ __forceinline__ float f2tf32(float x) {
    uint32_t u; asm("cvt.rna.tf32.f32 %0, %1;" : "=r"(u) : "f"(x));
    return __uint_as_float(u);
}

// m16n8k8 tf32 mma: A row-major frag (4 regs), B col-major frag (2 regs), C f32 (4 regs)
__device__ __forceinline__ void mma8(float* c, float4 a, float2 b) {
    asm volatile(
        "mma.sync.aligned.m16n8k8.row.col.f32.tf32.tf32.f32 "
        "{%0,%1,%2,%3}, {%4,%5,%6,%7}, {%8,%9}, {%0,%1,%2,%3};"
        : "+f"(c[0]), "+f"(c[1]), "+f"(c[2]), "+f"(c[3])
        : "r"(__float_as_uint(a.x)), "r"(__float_as_uint(a.y)),
          "r"(__float_as_uint(a.z)), "r"(__float_as_uint(a.w)),
          "r"(__float_as_uint(b.x)), "r"(__float_as_uint(b.y)));
}

// ---------------- utility kernels ----------------
__global__ void zero_kernel(float* __restrict__ p, int n) {
    int i = blockIdx.x * 256 + threadIdx.x;
    if (i < n) p[i] = 0.0f;
}

// W in: (512, Cin, 3, 3), row n = g*128+ch. Out: fragment-ordered B for mma.
// layout: [ny(4)][ck(K/32)][ks(4)][nt(16)][lane(32)][j(2)], n' = ch*4+g, k = tap*Cin+ci
__global__ void wfrag_kernel(const float* __restrict__ W, float* __restrict__ out, int Cin) {
    int K = Cin * 9;
    int NCH = K >> 5;
    int k = blockIdx.x * 256 + threadIdx.x;
    int np = blockIdx.y;
    if (k >= K) return;
    int ch = np >> 2, g = np & 3;
    int tap = k / Cin, ci = k - tap * Cin;
    float v = f2tf32(W[(size_t)(g * 128 + ch) * K + ci * 9 + tap]);
    int ny = np >> 7, nl = np & 127, nt = nl >> 3, rn = nl & 7;
    int ck = k >> 5, kl = k & 31, ks = kl >> 3, rk = kl & 7;
    int lane = rn * 4 + (rk & 3), j = rk >> 2;
    size_t off = ((((size_t)(ny * NCH + ck) * 4 + ks) * 16 + nt) * 32 + lane) * 2 + j;
    out[off] = v;
}

__global__ void bias_prep_kernel(const float* __restrict__ b, float* __restrict__ bp) {
    int np = blockIdx.x * 256 + threadIdx.x;
    if (np < NOUT) bp[np] = b[(np & 3) * 128 + (np >> 2)];
}

// layer 1 pack: concat(x1[t], x2[t], h1) -> padded (B, 384, 34, 34), tf32-rounded
__global__ void pack_l1_kernel(const float* __restrict__ x1, const float* __restrict__ x2, int t) {
    int idx = blockIdx.x * 256 + threadIdx.x;
    if (idx >= BATCH * CIN1 * NPIX) return;
    int pix = idx & 1023;
    int ci  = (idx >> 10) % CIN1;
    int b   = idx / (CIN1 * NPIX);
    float v;
    if (ci < 128)       v = x1[((b * TT + t) * NF + ci) * NPIX + pix];
    else if (ci < 256)  v = x2[((b * TT + t) * NF + (ci - 128)) * NPIX + pix];
    else                v = g_h1[(b * NF + (ci - 256)) * NPIX + pix];
    int y = pix >> 5, x = pix & 31;
    g_ipad[((b * CIN1 + ci) * HP + y + 1) * HP + x + 1] = f2tf32(v);
}

__global__ void pack_l23_kernel(const float* __restrict__ lo, const float* __restrict__ hi) {
    int idx = blockIdx.x * 256 + threadIdx.x;
    if (idx >= BATCH * CIN23 * NPIX) return;
    int pix = idx & 1023;
    int ci  = (idx >> 10) % CIN23;
    int b   = idx / (CIN23 * NPIX);
    float v = (ci < 128) ? lo[(b * NF + ci) * NPIX + pix]
                         : hi[(b * NF + (ci - 128)) * NPIX + pix];
    int y = pix >> 5, x = pix & 31;
    g_ipad[((b * CIN23 + ci) * HP + y + 1) * HP + x + 1] = f2tf32(v);
}

// ---------------- loaders (global -> regs), stores (regs -> smem frag layout) ----
// A tile frag layout: [ks(4)][mt(8)][lane(32)][j(4)] floats; thread holds float4 =
// {A[m][k], A[m+8][k], A[m][k+4], A[m+8][k+4]}, m = w*16 + lane/4, k = g*8 + lane%4.
__device__ __forceinline__ void ldg_tiles(
    const float* __restrict__ ipb, const float* __restrict__ Bc, int Cin,
    int ck, int pix0, int w, int lane, int tid, float4 va[4], float4 vb[4])
{
#pragma unroll
    for (int g = 0; g < 4; ++g) {
        int k0 = (ck << 5) + (g << 3) + (lane & 3);
        int ta = k0 / Cin, ca = k0 - ta * Cin;
        int kb = k0 + 4;
        int tb = kb / Cin, cb = kb - tb * Cin;
        int kha = ta / 3, kwa = ta - kha * 3;
        int khb = tb / 3, kwb = tb - khb * 3;
        int pix  = pix0 + (w << 4) + (lane >> 2);
        int y0 = pix >> 5, x0 = pix & 31;
        int pix8 = pix + 8;
        int y8 = pix8 >> 5, x8 = pix8 & 31;
        const float* pa = ipb + (size_t)ca * PLANE + kha * HP + kwa;
        const float* pb = ipb + (size_t)cb * PLANE + khb * HP + kwb;
        va[g].x = pa[y0 * HP + x0];
        va[g].y = pa[y8 * HP + x8];
        va[g].z = pb[y0 * HP + x0];
        va[g].w = pb[y8 * HP + x8];
    }
    const float4* sB = (const float4*)(Bc + ((size_t)ck << 12)) + (tid << 2);
#pragma unroll
    for (int q = 0; q < 4; ++q) vb[q] = sB[q];
}

__device__ __forceinline__ void sts_tiles(
    float* __restrict__ As, float* __restrict__ Bs,
    int w, int lane, int tid, const float4 va[4], const float4 vb[4])
{
    float4* dA = (float4*)As;
#pragma unroll
    for (int g = 0; g < 4; ++g) dA[((g << 3) + w) * 32 + lane] = va[g];
    float4* dB = (float4*)Bs + (tid << 2);
#pragma unroll
    for (int q = 0; q < 4; ++q) dB[q] = vb[q];
}

__device__ __forceinline__ void compute_chunk(
    const float* __restrict__ As, const float* __restrict__ Bs,
    int wm, int wn, int lane, float acc[4][4][4])
{
#pragma unroll
    for (int ks = 0; ks < 4; ++ks) {
        float4 af[4];
        float2 bf[4];
#pragma unroll
        for (int i = 0; i < 4; ++i)
            af[i] = *(const float4*)(As + ((((ks << 3) + (wm << 2) + i)) << 7) + (lane << 2));
#pragma unroll
        for (int jn = 0; jn < 4; ++jn)
            bf[jn] = *(const float2*)(Bs + (((ks << 4) + (wn << 2) + jn) << 6) + (lane << 1));
#pragma unroll
        for (int i = 0; i < 4; ++i)
#pragma unroll
            for (int jn = 0; jn < 4; ++jn)
                mma8(acc[i][jn], af[i], bf[jn]);
    }
}

// ---------------- TF32 HMMA GEMM + fused LSTM epilogue ----------------
// grid (32, 4), 256 threads. Z[m][n'] then gates -> c/h update.
__global__ void __launch_bounds__(256)
gemm_lstm_kernel(const float* __restrict__ Ip, const float* __restrict__ Bf,
                 const float* __restrict__ bp, float* __restrict__ c_st,
                 float* __restrict__ h_st, int Cin)
{
    extern __shared__ float sm[];
    float* Abuf[2] = { sm,        sm + 4096 };
    float* Bbuf[2] = { sm + 8192, sm + 12288 };

    const int tid = threadIdx.x, w = tid >> 5, lane = tid & 31;
    const int K = Cin * 9, NCH = K >> 5;
    const int m0 = blockIdx.x * BM, b = m0 >> 10, pix0 = m0 & 1023;
    const int ny = blockIdx.y, n0 = ny * BN;
    const float* ipb = Ip + (size_t)b * Cin * PLANE;
    const float* Bc  = Bf + (size_t)ny * NCH * 4096;
    const int wm = w >> 2, wn = w & 3;

    float acc[4][4][4];
#pragma unroll
    for (int i = 0; i < 4; ++i)
#pragma unroll
        for (int jn = 0; jn < 4; ++jn)
#pragma unroll
            for (int q = 0; q < 4; ++q) acc[i][jn][q] = 0.0f;

    float4 va[4], vb[4];
    ldg_tiles(ipb, Bc, Cin, 0, pix0, w, lane, tid, va, vb);
    sts_tiles(Abuf[0], Bbuf[0], w, lane, tid, va, vb);
    __syncthreads();

    for (int ck = 0; ck < NCH; ++ck) {
        const int cur = ck & 1;
        const bool more = (ck + 1 < NCH);
        if (more) ldg_tiles(ipb, Bc, Cin, ck + 1, pix0, w, lane, tid, va, vb);
        compute_chunk(Abuf[cur], Bbuf[cur], wm, wn, lane, acc);
        if (more) {
            sts_tiles(Abuf[cur ^ 1], Bbuf[cur ^ 1], w, lane, tid, va, vb);
            __syncthreads();
        }
    }

    // ---- fused LSTM epilogue ----
    // D frag: c0(row,col) c1(row,col+1) c2(row+8,col) c3(row+8,col+1),
    // row = lane/4, col = (lane%4)*2. n' = ch*4+gate -> even lanes hold (i,f),
    // odd lanes hold (o,g) of the same channel; xor-1 shuffle combines them.
#pragma unroll
    for (int jn = 0; jn < 4; ++jn) {
        const int nc = n0 + (wn << 5) + (jn << 3) + ((lane & 3) << 1);
        const float b0 = __ldg(bp + nc), b1 = __ldg(bp + nc + 1);
        const float b2 = __ldg(bp + nc + 2), b3 = __ldg(bp + nc + 3);
        const int ch = nc >> 2;
#pragma unroll
        for (int i = 0; i < 4; ++i) {
#pragma unroll
            for (int rh = 0; rh < 2; ++rh) {
                float v0 = acc[i][jn][rh * 2 + 0];
                float v1 = acc[i][jn][rh * 2 + 1];
                float p0 = __shfl_xor_sync(0xffffffffu, v0, 1);
                float p1 = __shfl_xor_sync(0xffffffffu, v1, 1);
                if (!(lane & 1)) {
                    float zi = v0 + b0, zf = v1 + b1, zo = p0 + b2, zg = p1 + b3;
                    float gi = 1.0f / (1.0f + expf(-zi));
                    float gf = 1.0f / (1.0f + expf(-zf));
                    float go = 1.0f / (1.0f + expf(-zo));
                    float gg = tanhf(zg);
                    int mrow = pix0 + (wm << 6) + (i << 4) + (lane >> 2) + (rh << 3);
                    int s = ((b * NF + ch) << 10) + mrow;
                    float cn = gf * c_st[s] + gi * gg;
                    c_st[s] = cn;
                    h_st[s] = go * tanhf(cn);
                }
            }
        }
    }
}

__global__ void copy_out_kernel(float* __restrict__ out) {
    int i = blockIdx.x * 256 + threadIdx.x;
    if (i < BATCH * NF * NPIX) out[i] = g_h3[i];
}

// ---------------- launch ----------------
extern "C" void kernel_launch(void* const* d_in, const int* in_sizes, int n_in,
                              void* d_out, int out_size) {
    const float* x1 = (const float*)d_in[0];
    const float* x2 = (const float*)d_in[1];
    const float* W1 = (const float*)d_in[2];
    const float* b1 = (const float*)d_in[3];
    const float* W2 = (const float*)d_in[4];
    const float* b2 = (const float*)d_in[5];
    const float* W3 = (const float*)d_in[6];
    const float* b3 = (const float*)d_in[7];
    float* out = (float*)d_out;

    float *p_ipad, *p_h1, *p_c1, *p_h2, *p_c2, *p_h3, *p_c3;
    float *p_wf1, *p_wf2, *p_wf3, *p_bp1, *p_bp2, *p_bp3;
    cudaGetSymbolAddress((void**)&p_ipad, g_ipad);
    cudaGetSymbolAddress((void**)&p_h1, g_h1);
    cudaGetSymbolAddress((void**)&p_c1, g_c1);
    cudaGetSymbolAddress((void**)&p_h2, g_h2);
    cudaGetSymbolAddress((void**)&p_c2, g_c2);
    cudaGetSymbolAddress((void**)&p_h3, g_h3);
    cudaGetSymbolAddress((void**)&p_c3, g_c3);
    cudaGetSymbolAddress((void**)&p_wf1, g_wf1);
    cudaGetSymbolAddress((void**)&p_wf2, g_wf2);
    cudaGetSymbolAddress((void**)&p_wf3, g_wf3);
    cudaGetSymbolAddress((void**)&p_bp1, g_bp1);
    cudaGetSymbolAddress((void**)&p_bp2, g_bp2);
    cudaGetSymbolAddress((void**)&p_bp3, g_bp3);

    cudaFuncSetAttribute(gemm_lstm_kernel,
                         cudaFuncAttributeMaxDynamicSharedMemorySize, SMEM_DYN);

    const int ST = BATCH * NF * NPIX;
    const int IP = BATCH * CIN1 * PLANE;
    auto nb = [](int n) { return (n + 255) / 256; };

    zero_kernel<<<nb(IP), 256>>>(p_ipad, IP);
    zero_kernel<<<nb(ST), 256>>>(p_h1, ST);
    zero_kernel<<<nb(ST), 256>>>(p_c1, ST);
    zero_kernel<<<nb(ST), 256>>>(p_h2, ST);
    zero_kernel<<<nb(ST), 256>>>(p_c2, ST);
    zero_kernel<<<nb(ST), 256>>>(p_h3, ST);
    zero_kernel<<<nb(ST), 256>>>(p_c3, ST);

    wfrag_kernel<<<dim3(nb(K1), NOUT), 256>>>(W1, p_wf1, CIN1);
    wfrag_kernel<<<dim3(nb(K23), NOUT), 256>>>(W2, p_wf2, CIN23);
    wfrag_kernel<<<dim3(nb(K23), NOUT), 256>>>(W3, p_wf3, CIN23);
    bias_prep_kernel<<<2, 256>>>(b1, p_bp1);
    bias_prep_kernel<<<2, 256>>>(b2, p_bp2);
    bias_prep_kernel<<<2, 256>>>(b3, p_bp3);

    const dim3 ggrid(32, 4);
    const int NP1  = BATCH * CIN1 * NPIX;
    const int NP23 = BATCH * CIN23 * NPIX;

    for (int t = 0; t < TT; ++t) {
        pack_l1_kernel<<<nb(NP1), 256>>>(x1, x2, t);
        gemm_lstm_kernel<<<ggrid, 256, SMEM_DYN>>>(p_ipad, p_wf1, p_bp1, p_c1, p_h1, CIN1);

        pack_l23_kernel<<<nb(NP23), 256>>>(p_h1, p_h2);
        gemm_lstm_kernel<<<ggrid, 256, SMEM_DYN>>>(p_ipad, p_wf2, p_bp2, p_c2, p_h2, CIN23);

        pack_l23_kernel<<<nb(NP23), 256>>>(p_h2, p_h3);
        gemm_lstm_kernel<<<ggrid, 256, SMEM_DYN>>>(p_ipad, p_wf3, p_bp3, p_c3, p_h3, CIN23);
    }

    copy_out_kernel<<<nb(ST), 256>>>(out);
}

// round 6
// speedup vs baseline: 2.6000x; 1.4007x over previous
#include <cuda_runtime.h>
#include <cstdint>
#include <math.h>

// ---------------- problem constants ----------------
#define NF     128
#define BATCH  4
#define TT     8
#define NPIX   1024
#define CIN1   384
#define CIN23  256
#define K1     (CIN1 * 9)     // 3456
#define K23    (CIN23 * 9)    // 2304
#define NCH1   108
#define NCH23  72
#define PADPL  (34 * 36)      // 1224 padded plane (34 rows x 36 cols)

// pad buffer strides (floats)
#define XC   (BATCH * 256 * PADPL)     // 1253376, per-copy stride of padX
#define H1C  (BATCH * 128 * PADPL)     // 626688
#define H1P  (3 * H1C)                 // parity stride padH1
#define L2C  (BATCH * 256 * PADPL)     // 1253376
#define L2P  (3 * L2C)                 // parity stride padL2/padL3

// GEMM tiling: CTA 64x128x32, 4 warps (2m x 2n), warp tile 32x64, mma m16n8k8
#define BM 64
#define STAGES 4
#define A_ST 2304              // 32 k-rows * 72 (stride-72 padding)
#define B_ST 4096              // 128 n * 32 k
#define STG  (A_ST + B_ST)     // 6400 floats per stage
#define SMEM_DYN (STAGES * STG * 4)   // 102400 B

// ---------------- persistent device scratch ----------------
__device__ __align__(256) float g_padX[3 * XC];
__device__ __align__(256) float g_padH1[2 * H1P];
__device__ __align__(256) float g_padL2[2 * L2P];
__device__ __align__(256) float g_padL3[2 * L2P];
__device__ __align__(256) float g_c1[BATCH * NF * NPIX];
__device__ __align__(256) float g_c2[BATCH * NF * NPIX];
__device__ __align__(256) float g_c3[BATCH * NF * NPIX];
__device__ __align__(256) float g_wf1[K1 * 512];
__device__ __align__(256) float g_wf2[K23 * 512];
__device__ __align__(256) float g_wf3[K23 * 512];
__device__ float g_bp1[512];
__device__ float g_bp2[512];
__device__ float g_bp3[512];

__device__ __forceinline__ float f2tf32(float x) {
    uint32_t u; asm("cvt.rna.tf32.f32 %0, %1;" : "=r"(u) : "f"(x));
    return __uint_as_float(u);
}
__device__ __forceinline__ uint32_t smem_u32(const void* p) {
    uint32_t a;
    asm("{ .reg .u64 t; cvta.to.shared.u64 t, %1; cvt.u32.u64 %0, t; }" : "=r"(a) : "l"(p));
    return a;
}
#define CP_ASYNC16(dst, src) \
    asm volatile("cp.async.cg.shared.global [%0], [%1], 16;" :: "r"(dst), "l"(src))
#define CP_COMMIT() asm volatile("cp.async.commit_group;" ::: "memory")
#define CP_WAIT(n)  asm volatile("cp.async.wait_group %0;" :: "n"(n) : "memory")

__device__ __forceinline__ void mma8(float* c, float4 a, float2 b) {
    asm volatile(
        "mma.sync.aligned.m16n8k8.row.col.f32.tf32.tf32.f32 "
        "{%0,%1,%2,%3}, {%4,%5,%6,%7}, {%8,%9}, {%0,%1,%2,%3};"
        : "+f"(c[0]), "+f"(c[1]), "+f"(c[2]), "+f"(c[3])
        : "r"(__float_as_uint(a.x)), "r"(__float_as_uint(a.y)),
          "r"(__float_as_uint(a.z)), "r"(__float_as_uint(a.w)),
          "r"(__float_as_uint(b.x)), "r"(__float_as_uint(b.y)));
}

// ---------------- init: zero all pads + c-states (1 launch) ----------------
__global__ void init_kernel() {
    long i = (long)blockIdx.x * 256 + threadIdx.x;
    long n;
    n = 3L * XC;      if (i < n) { g_padX[i] = 0.0f; return; }  i -= n;
    n = 2L * H1P;     if (i < n) { g_padH1[i] = 0.0f; return; } i -= n;
    n = 2L * L2P;     if (i < n) { g_padL2[i] = 0.0f; return; } i -= n;
    n = 2L * L2P;     if (i < n) { g_padL3[i] = 0.0f; return; } i -= n;
    n = BATCH * NF * NPIX;
    if (i < n) { g_c1[i] = 0.0f; return; } i -= n;
    if (i < n) { g_c2[i] = 0.0f; return; } i -= n;
    if (i < n) { g_c3[i] = 0.0f; return; }
}
#define INIT_TOTAL (3L*XC + 2L*H1P + 4L*L2P + 3L*BATCH*NF*NPIX)

// ---------------- weight prep: fragment-ordered gmem (1 launch) ----------------
// dest: [ny4][ck][wn2][ks4][nf2 4][lane32][f2][j2]
__device__ __forceinline__ void wstore(const float* __restrict__ W, float* __restrict__ out,
                                       int np, int k, int Cin, int NCH) {
    int K = Cin * 9;
    int ch = np >> 2, g = np & 3;
    int tap = k / Cin, ci = k - tap * Cin;
    float v = f2tf32(W[(size_t)(g * 128 + ch) * K + ci * 9 + tap]);
    int ny = np >> 7, n_t = np & 127;
    int wn = n_t >> 6, nl = n_t & 63;
    int nf = nl >> 3, rn = nl & 7, nf2 = nf >> 1, f = nf & 1;
    int ck = k >> 5, kl = k & 31, ks = kl >> 3, rk = kl & 7;
    int lane = rn * 4 + (rk & 3), j = rk >> 2;
    size_t off = (size_t)ny * NCH * 4096 + (size_t)ck * 4096 + wn * 2048
               + ks * 512 + nf2 * 128 + lane * 4 + f * 2 + j;
    out[off] = v;
}
__global__ void wprep_kernel(const float* __restrict__ W1, const float* __restrict__ b1,
                             const float* __restrict__ W2, const float* __restrict__ b2,
                             const float* __restrict__ W3, const float* __restrict__ b3) {
    int idx = blockIdx.x * 256 + threadIdx.x;
    if (idx < 512) {
        int src = (idx & 3) * 128 + (idx >> 2);
        g_bp1[idx] = b1[src]; g_bp2[idx] = b2[src]; g_bp3[idx] = b3[src];
    }
    if (idx >= K1 * 512) return;
    int np = idx & 511, k = idx >> 9;
    wstore(W1, g_wf1, np, k, CIN1, NCH1);
    if (k < K23) {
        wstore(W2, g_wf2, np, k, CIN23, NCH23);
        wstore(W3, g_wf3, np, k, CIN23, NCH23);
    }
}

// ---------------- per-step x pack: 3 shifted copies (8 launches) ----------------
__global__ void pack_x_kernel(const float* __restrict__ x1, const float* __restrict__ x2, int t) {
    int idx = blockIdx.x * 256 + threadIdx.x;       // over BATCH*256*NPIX
    if (idx >= BATCH * 256 * NPIX) return;
    int pix = idx & 1023;
    int ci  = (idx >> 10) & 255;
    int b   = idx >> 18;
    float v = (ci < 128) ? x1[((b * TT + t) * NF + ci) * NPIX + pix]
                         : x2[((b * TT + t) * NF + (ci - 128)) * NPIX + pix];
    v = f2tf32(v);
    int plane = (b << 8) + ci;
    int py = (pix >> 5) + 1, px = (pix & 31) + 1;
    int base = (plane * 34 + py) * 36 + px;
#pragma unroll
    for (int c = 0; c < 3; ++c)
        if (px - c >= 0) g_padX[c * XC + base - c] = v;
}

// ---------------- fused GEMM + LSTM kernel ----------------
// grid (64, 4), 128 threads. Z[m][n'] = sum_k A[m][k]*B[n'][k]; n' = ch*4+gate.
__global__ void __launch_bounds__(128)
gemm_lstm_kernel(const float* __restrict__ Bf, const float* __restrict__ bp,
                 float* __restrict__ c_st, float* __restrict__ h_out,
                 int Cin, int NCH, int layer, int par)
{
    extern __shared__ float sm[];
    const uint32_t sb = smem_u32(sm);

    const int tid = threadIdx.x, w = tid >> 5, lane = tid & 31;
    const int wm = w >> 1, wn = w & 1, lane4 = lane & 3;
    const int m0 = blockIdx.x * BM, b = m0 >> 10, pix0 = m0 & 1023;
    const int ny = blockIdx.y;
    const float* Bny = Bf + (size_t)ny * NCH * 4096;

    // loader coords
    const int kl8 = tid >> 4;            // 0..7 base k row
    const int m4  = (tid & 15) << 2;     // m position (float4)
    const int pixL = pix0 + m4;
    const int yL = pixL >> 5, xL = pixL & 31;

    float acc[2][8][4];
#pragma unroll
    for (int i = 0; i < 2; ++i)
#pragma unroll
        for (int jn = 0; jn < 8; ++jn)
#pragma unroll
            for (int q = 0; q < 4; ++q) acc[i][jn][q] = 0.0f;

    // ---- stage issue ----
    auto issue = [&](int ck, int s) {
        const uint32_t stA = sb + (s * STG) * 4;
        const uint32_t stB = stA + A_ST * 4;
#pragma unroll
        for (int jj = 0; jj < 4; ++jj) {
            const int krow = kl8 + (jj << 3);
            const int kg = (ck << 5) + krow;
            const int tap = kg / Cin;
            const int ci  = kg - tap * Cin;
            const int kh = tap / 3, kw = tap - kh * 3;
            const int row = yL + kh;
            const float* src;
            if (layer == 1) {
                if (ci < 256)
                    src = g_padX + (size_t)kw * XC + (((b << 8) + ci) * 34 + row) * 36 + xL;
                else
                    src = g_padH1 + (size_t)par * H1P + (size_t)kw * H1C
                        + (((b << 7) + ci - 256) * 34 + row) * 36 + xL;
            } else if (layer == 2) {
                src = g_padL2 + (size_t)par * L2P + (size_t)kw * L2C
                    + (((b << 8) + ci) * 34 + row) * 36 + xL;
            } else {
                src = g_padL3 + (size_t)par * L2P + (size_t)kw * L2C
                    + (((b << 8) + ci) * 34 + row) * 36 + xL;
            }
            CP_ASYNC16(stA + (krow * 72 + m4) * 4, src);
        }
        const float* bsrc = Bny + ((size_t)ck << 12) + (tid << 2);
#pragma unroll
        for (int q = 0; q < 8; ++q)
            CP_ASYNC16(stB + (((q << 7) + tid) << 4), bsrc + (q << 9));
        CP_COMMIT();
    };

    // ---- pipeline ----
#pragma unroll
    for (int s = 0; s < STAGES - 1; ++s) issue(s, s);

    for (int ck = 0; ck < NCH; ++ck) {
        CP_WAIT(STAGES - 2);
        __syncthreads();
        const int nx = ck + STAGES - 1;
        if (nx < NCH) issue(nx, nx & (STAGES - 1));

        const float* As = sm + (ck & (STAGES - 1)) * STG;
        const float* Bs = As + A_ST + (wn << 11);
#pragma unroll
        for (int ks = 0; ks < 4; ++ks) {
            const int kq = (ks << 3) + lane4;
            float4 af[2];
#pragma unroll
            for (int mf = 0; mf < 2; ++mf) {
                const int mrow = (wm << 5) + (mf << 4) + (lane >> 2);
                af[mf].x = As[kq * 72 + mrow];
                af[mf].y = As[kq * 72 + mrow + 8];
                af[mf].z = As[(kq + 4) * 72 + mrow];
                af[mf].w = As[(kq + 4) * 72 + mrow + 8];
            }
#pragma unroll
            for (int nf2 = 0; nf2 < 4; ++nf2) {
                const float4 bv = *(const float4*)(Bs + (ks << 9) + (nf2 << 7) + (lane << 2));
                const float2 b0 = make_float2(bv.x, bv.y);
                const float2 b1 = make_float2(bv.z, bv.w);
                mma8(acc[0][nf2 * 2],     af[0], b0);
                mma8(acc[0][nf2 * 2 + 1], af[0], b1);
                mma8(acc[1][nf2 * 2],     af[1], b0);
                mma8(acc[1][nf2 * 2 + 1], af[1], b1);
            }
        }
    }

    // ---- fused LSTM epilogue + pad writes for downstream consumers ----
#pragma unroll
    for (int nf = 0; nf < 8; ++nf) {
        const int nc = (ny << 7) + (wn << 6) + (nf << 3) + (lane4 << 1);
        const float bb0 = __ldg(bp + nc),     bb1 = __ldg(bp + nc + 1);
        const float bb2 = __ldg(bp + nc + 2), bb3 = __ldg(bp + nc + 3);
        const int ch = nc >> 2;
#pragma unroll
        for (int mf = 0; mf < 2; ++mf) {
#pragma unroll
            for (int rh = 0; rh < 2; ++rh) {
                float v0 = acc[mf][nf][rh * 2 + 0];
                float v1 = acc[mf][nf][rh * 2 + 1];
                float p0 = __shfl_xor_sync(0xffffffffu, v0, 1);
                float p1 = __shfl_xor_sync(0xffffffffu, v1, 1);
                if (!(lane & 1)) {
                    const float zi = v0 + bb0, zf = v1 + bb1, zo = p0 + bb2, zg = p1 + bb3;
                    const float gi = 1.0f / (1.0f + expf(-zi));
                    const float gf = 1.0f / (1.0f + expf(-zf));
                    const float go = 1.0f / (1.0f + expf(-zo));
                    const float gg = tanhf(zg);
                    const int pixm = pix0 + (wm << 5) + (mf << 4) + (lane >> 2) + (rh << 3);
                    const int sidx = ((((b << 7) + ch)) << 10) + pixm;
                    const float cn = gf * c_st[sidx] + gi * gg;
                    c_st[sidx] = cn;
                    const float hn = go * tanhf(cn);
                    const float hr = f2tf32(hn);
                    const int py = (pixm >> 5) + 1, px = (pixm & 31) + 1;
                    if (layer == 1) {
                        const int o1 = ((b << 7) + ch) * 34 + py;
                        const int o2 = ((b << 8) + ch) * 34 + py;
                        const size_t p1b = (size_t)(par ^ 1) * H1P;
                        const size_t p2b = (size_t)par * L2P;
#pragma unroll
                        for (int c = 0; c < 3; ++c) if (px - c >= 0) {
                            g_padH1[p1b + (size_t)c * H1C + o1 * 36 + px - c] = hr;
                            g_padL2[p2b + (size_t)c * L2C + o2 * 36 + px - c] = hr;
                        }
                    } else if (layer == 2) {
                        const int o2 = ((b << 8) + 128 + ch) * 34 + py;
                        const int o3 = ((b << 8) + ch) * 34 + py;
                        const size_t p2b = (size_t)(par ^ 1) * L2P;
                        const size_t p3b = (size_t)par * L2P;
#pragma unroll
                        for (int c = 0; c < 3; ++c) if (px - c >= 0) {
                            g_padL2[p2b + (size_t)c * L2C + o2 * 36 + px - c] = hr;
                            g_padL3[p3b + (size_t)c * L2C + o3 * 36 + px - c] = hr;
                        }
                    } else {
                        const int o3 = ((b << 8) + 128 + ch) * 34 + py;
                        const size_t p3b = (size_t)(par ^ 1) * L2P;
#pragma unroll
                        for (int c = 0; c < 3; ++c) if (px - c >= 0)
                            g_padL3[p3b + (size_t)c * L2C + o3 * 36 + px - c] = hr;
                        h_out[sidx] = hn;
                    }
                }
            }
        }
    }
}

// ---------------- launch ----------------
extern "C" void kernel_launch(void* const* d_in, const int* in_sizes, int n_in,
                              void* d_out, int out_size) {
    const float* x1 = (const float*)d_in[0];
    const float* x2 = (const float*)d_in[1];
    const float* W1 = (const float*)d_in[2];
    const float* b1 = (const float*)d_in[3];
    const float* W2 = (const float*)d_in[4];
    const float* b2 = (const float*)d_in[5];
    const float* W3 = (const float*)d_in[6];
    const float* b3 = (const float*)d_in[7];
    float* out = (float*)d_out;

    float *p_c1, *p_c2, *p_c3, *p_wf1, *p_wf2, *p_wf3, *p_bp1, *p_bp2, *p_bp3;
    cudaGetSymbolAddress((void**)&p_c1, g_c1);
    cudaGetSymbolAddress((void**)&p_c2, g_c2);
    cudaGetSymbolAddress((void**)&p_c3, g_c3);
    cudaGetSymbolAddress((void**)&p_wf1, g_wf1);
    cudaGetSymbolAddress((void**)&p_wf2, g_wf2);
    cudaGetSymbolAddress((void**)&p_wf3, g_wf3);
    cudaGetSymbolAddress((void**)&p_bp1, g_bp1);
    cudaGetSymbolAddress((void**)&p_bp2, g_bp2);
    cudaGetSymbolAddress((void**)&p_bp3, g_bp3);

    cudaFuncSetAttribute(gemm_lstm_kernel,
                         cudaFuncAttributeMaxDynamicSharedMemorySize, SMEM_DYN);

    const dim3 ggrid(64, 4);
    const int initBlocks = (int)((INIT_TOTAL + 255) / 256);

    init_kernel<<<initBlocks, 256>>>();
    wprep_kernel<<<(K1 * 512 + 255) / 256, 256>>>(W1, b1, W2, b2, W3, b3);

    for (int t = 0; t < TT; ++t) {
        const int par = t & 1;
        pack_x_kernel<<<(BATCH * 256 * NPIX + 255) / 256, 256>>>(x1, x2, t);
        gemm_lstm_kernel<<<ggrid, 128, SMEM_DYN>>>(p_wf1, p_bp1, p_c1, nullptr,
                                                   CIN1, NCH1, 1, par);
        gemm_lstm_kernel<<<ggrid, 128, SMEM_DYN>>>(p_wf2, p_bp2, p_c2, nullptr,
                                                   CIN23, NCH23, 2, par);
        gemm_lstm_kernel<<<ggrid, 128, SMEM_DYN>>>(p_wf3, p_bp3, p_c3, out,
                                                   CIN23, NCH23, 3, par);
    }
}

// round 7
// speedup vs baseline: 3.3244x; 1.2786x over previous
#include <cuda_runtime.h>
#include <cstdint>
#include <math.h>

// ---------------- problem constants ----------------
#define NF     128
#define BATCH  4
#define TT     8
#define NPIX   1024
#define CIN1   384
#define CIN23  256
#define K1     (CIN1 * 9)     // 3456
#define K23    (CIN23 * 9)    // 2304
#define NCH1   108
#define NCH23  72
#define PADPL  (34 * 36)      // 1224 padded plane (34 rows x 36 cols)

// pad buffer strides (floats)
#define XC   (BATCH * 256 * PADPL)     // 1253376, per-copy stride of padX
#define H1C  (BATCH * 128 * PADPL)     // 626688
#define H1P  (3 * H1C)                 // parity stride padH1
#define L2C  (BATCH * 256 * PADPL)     // 1253376
#define L2P  (3 * L2C)                 // parity stride padL2/padL3

// GEMM tiling: CTA 64x128x32, 8 warps (2m x 4n), warp tile 32x32, mma m16n8k8
#define BM 64
#define STAGES 4
#define A_ST 2304              // 32 k-rows * 72 (stride-72 padding)
#define B_ST 4096              // 128 n * 32 k
#define STG  (A_ST + B_ST)     // 6400 floats per stage
#define SMEM_DYN (STAGES * STG * 4)   // 102400 B

// ---------------- persistent device scratch ----------------
__device__ __align__(256) float g_padX[3 * XC];
__device__ __align__(256) float g_padH1[2 * H1P];
__device__ __align__(256) float g_padL2[2 * L2P];
__device__ __align__(256) float g_padL3[2 * L2P];
__device__ __align__(256) float g_c1[BATCH * NF * NPIX];
__device__ __align__(256) float g_c2[BATCH * NF * NPIX];
__device__ __align__(256) float g_c3[BATCH * NF * NPIX];
__device__ __align__(256) float g_wf1[K1 * 512];
__device__ __align__(256) float g_wf2[K23 * 512];
__device__ __align__(256) float g_wf3[K23 * 512];
__device__ float g_bp1[512];
__device__ float g_bp2[512];
__device__ float g_bp3[512];

__device__ __forceinline__ float f2tf32(float x) {
    uint32_t u; asm("cvt.rna.tf32.f32 %0, %1;" : "=r"(u) : "f"(x));
    return __uint_as_float(u);
}
__device__ __forceinline__ uint32_t smem_u32(const void* p) {
    uint32_t a;
    asm("{ .reg .u64 t; cvta.to.shared.u64 t, %1; cvt.u32.u64 %0, t; }" : "=r"(a) : "l"(p));
    return a;
}
#define CP_ASYNC16(dst, src) \
    asm volatile("cp.async.cg.shared.global [%0], [%1], 16;" :: "r"(dst), "l"(src))
#define CP_COMMIT() asm volatile("cp.async.commit_group;" ::: "memory")
#define CP_WAIT(n)  asm volatile("cp.async.wait_group %0;" :: "n"(n) : "memory")

__device__ __forceinline__ void mma8(float* c, float4 a, float2 b) {
    asm volatile(
        "mma.sync.aligned.m16n8k8.row.col.f32.tf32.tf32.f32 "
        "{%0,%1,%2,%3}, {%4,%5,%6,%7}, {%8,%9}, {%0,%1,%2,%3};"
        : "+f"(c[0]), "+f"(c[1]), "+f"(c[2]), "+f"(c[3])
        : "r"(__float_as_uint(a.x)), "r"(__float_as_uint(a.y)),
          "r"(__float_as_uint(a.z)), "r"(__float_as_uint(a.w)),
          "r"(__float_as_uint(b.x)), "r"(__float_as_uint(b.y)));
}

// ---------------- init: zero all pads + c-states (1 launch) ----------------
__global__ void init_kernel() {
    long i = (long)blockIdx.x * 256 + threadIdx.x;
    long n;
    n = 3L * XC;      if (i < n) { g_padX[i] = 0.0f; return; }  i -= n;
    n = 2L * H1P;     if (i < n) { g_padH1[i] = 0.0f; return; } i -= n;
    n = 2L * L2P;     if (i < n) { g_padL2[i] = 0.0f; return; } i -= n;
    n = 2L * L2P;     if (i < n) { g_padL3[i] = 0.0f; return; } i -= n;
    n = BATCH * NF * NPIX;
    if (i < n) { g_c1[i] = 0.0f; return; } i -= n;
    if (i < n) { g_c2[i] = 0.0f; return; } i -= n;
    if (i < n) { g_c3[i] = 0.0f; return; }
}
#define INIT_TOTAL (3L*XC + 2L*H1P + 4L*L2P + 3L*BATCH*NF*NPIX)

// ---------------- weight prep: fragment-ordered gmem (1 launch) ----------------
// dest: [ny4][ck][wn4][ks4][nf2 2][lane32][f2][j2]
__device__ __forceinline__ void wstore(const float* __restrict__ W, float* __restrict__ out,
                                       int np, int k, int Cin, int NCH) {
    int K = Cin * 9;
    int ch = np >> 2, g = np & 3;
    int tap = k / Cin, ci = k - tap * Cin;
    float v = f2tf32(W[(size_t)(g * 128 + ch) * K + ci * 9 + tap]);
    int ny = np >> 7, n_t = np & 127;
    int wn = n_t >> 5, nl = n_t & 31;
    int nf = nl >> 3, rn = nl & 7, nf2 = nf >> 1, f = nf & 1;
    int ck = k >> 5, kl = k & 31, ks = kl >> 3, rk = kl & 7;
    int lane = rn * 4 + (rk & 3), j = rk >> 2;
    size_t off = (size_t)ny * NCH * 4096 + (size_t)ck * 4096 + wn * 1024
               + ks * 256 + nf2 * 128 + lane * 4 + f * 2 + j;
    out[off] = v;
}
__global__ void wprep_kernel(const float* __restrict__ W1, const float* __restrict__ b1,
                             const float* __restrict__ W2, const float* __restrict__ b2,
                             const float* __restrict__ W3, const float* __restrict__ b3) {
    int idx = blockIdx.x * 256 + threadIdx.x;
    if (idx < 512) {
        int src = (idx & 3) * 128 + (idx >> 2);
        g_bp1[idx] = b1[src]; g_bp2[idx] = b2[src]; g_bp3[idx] = b3[src];
    }
    if (idx >= K1 * 512) return;
    int np = idx & 511, k = idx >> 9;
    wstore(W1, g_wf1, np, k, CIN1, NCH1);
    if (k < K23) {
        wstore(W2, g_wf2, np, k, CIN23, NCH23);
        wstore(W3, g_wf3, np, k, CIN23, NCH23);
    }
}

// ---------------- per-step x pack: 3 shifted copies (8 launches) ----------------
__global__ void pack_x_kernel(const float* __restrict__ x1, const float* __restrict__ x2, int t) {
    int idx = blockIdx.x * 256 + threadIdx.x;       // over BATCH*256*NPIX
    if (idx >= BATCH * 256 * NPIX) return;
    int pix = idx & 1023;
    int ci  = (idx >> 10) & 255;
    int b   = idx >> 18;
    float v = (ci < 128) ? x1[((b * TT + t) * NF + ci) * NPIX + pix]
                         : x2[((b * TT + t) * NF + (ci - 128)) * NPIX + pix];
    v = f2tf32(v);
    int plane = (b << 8) + ci;
    int py = (pix >> 5) + 1, px = (pix & 31) + 1;
    int base = (plane * 34 + py) * 36 + px;
#pragma unroll
    for (int c = 0; c < 3; ++c)
        if (px - c >= 0) g_padX[c * XC + base - c] = v;
}

// ---------------- fused GEMM + LSTM kernel ----------------
// grid (64, 4), 256 threads (8 warps, 2m x 4n). Z[m][n'] = sum_k A[m][k]*B[n'][k].
__global__ void __launch_bounds__(256, 2)
gemm_lstm_kernel(const float* __restrict__ Bf, const float* __restrict__ bp,
                 float* __restrict__ c_st, float* __restrict__ h_out,
                 int Cin, int NCH, int layer, int par)
{
    extern __shared__ float sm[];
    const uint32_t sb = smem_u32(sm);

    const int tid = threadIdx.x, w = tid >> 5, lane = tid & 31;
    const int wm = w >> 2, wn = w & 3, lane4 = lane & 3;
    const int m0 = blockIdx.x * BM, b = m0 >> 10, pix0 = m0 & 1023;
    const int ny = blockIdx.y;
    const float* Bny = Bf + (size_t)ny * NCH * 4096;

    // A loader coords: thread covers krow0 and krow0+16, m-float4 at m4
    const int kl16 = tid >> 4;           // 0..15 base k row
    const int m4   = (tid & 15) << 2;    // m position (float4)
    const int pixL = pix0 + m4;
    const int yL = pixL >> 5, xL = pixL & 31;

    float acc[2][4][4];
#pragma unroll
    for (int i = 0; i < 2; ++i)
#pragma unroll
        for (int jn = 0; jn < 4; ++jn)
#pragma unroll
            for (int q = 0; q < 4; ++q) acc[i][jn][q] = 0.0f;

    // ---- stage issue ----
    auto issue = [&](int ck, int s) {
        const uint32_t stA = sb + (s * STG) * 4;
        const uint32_t stB = stA + A_ST * 4;
#pragma unroll
        for (int jj = 0; jj < 2; ++jj) {
            const int krow = kl16 + (jj << 4);
            const int kg = (ck << 5) + krow;
            const int tap = kg / Cin;
            const int ci  = kg - tap * Cin;
            const int kh = tap / 3, kw = tap - kh * 3;
            const int row = yL + kh;
            const float* src;
            if (layer == 1) {
                if (ci < 256)
                    src = g_padX + (size_t)kw * XC + (((b << 8) + ci) * 34 + row) * 36 + xL;
                else
                    src = g_padH1 + (size_t)par * H1P + (size_t)kw * H1C
                        + (((b << 7) + ci - 256) * 34 + row) * 36 + xL;
            } else if (layer == 2) {
                src = g_padL2 + (size_t)par * L2P + (size_t)kw * L2C
                    + (((b << 8) + ci) * 34 + row) * 36 + xL;
            } else {
                src = g_padL3 + (size_t)par * L2P + (size_t)kw * L2C
                    + (((b << 8) + ci) * 34 + row) * 36 + xL;
            }
            CP_ASYNC16(stA + (krow * 72 + m4) * 4, src);
        }
        const float* bsrc = Bny + ((size_t)ck << 12) + (tid << 2);
#pragma unroll
        for (int q = 0; q < 4; ++q)
            CP_ASYNC16(stB + (((q << 8) + tid) << 4), bsrc + (q << 10));
        CP_COMMIT();
    };

    // ---- pipeline ----
#pragma unroll
    for (int s = 0; s < STAGES - 1; ++s) issue(s, s);

    for (int ck = 0; ck < NCH; ++ck) {
        CP_WAIT(STAGES - 2);
        __syncthreads();
        const int nx = ck + STAGES - 1;
        if (nx < NCH) issue(nx, nx & (STAGES - 1));

        const float* As = sm + (ck & (STAGES - 1)) * STG;
        const float* Bs = As + A_ST + (wn << 10);
#pragma unroll
        for (int ks = 0; ks < 4; ++ks) {
            const int kq = (ks << 3) + lane4;
            float4 af[2];
#pragma unroll
            for (int mf = 0; mf < 2; ++mf) {
                const int mrow = (wm << 5) + (mf << 4) + (lane >> 2);
                af[mf].x = As[kq * 72 + mrow];
                af[mf].y = As[kq * 72 + mrow + 8];
                af[mf].z = As[(kq + 4) * 72 + mrow];
                af[mf].w = As[(kq + 4) * 72 + mrow + 8];
            }
#pragma unroll
            for (int nf2 = 0; nf2 < 2; ++nf2) {
                const float4 bv = *(const float4*)(Bs + (ks << 8) + (nf2 << 7) + (lane << 2));
                const float2 b0 = make_float2(bv.x, bv.y);
                const float2 b1 = make_float2(bv.z, bv.w);
                mma8(acc[0][nf2 * 2],     af[0], b0);
                mma8(acc[0][nf2 * 2 + 1], af[0], b1);
                mma8(acc[1][nf2 * 2],     af[1], b0);
                mma8(acc[1][nf2 * 2 + 1], af[1], b1);
            }
        }
    }

    // ---- fused LSTM epilogue + pad writes for downstream consumers ----
#pragma unroll
    for (int nf = 0; nf < 4; ++nf) {
        const int nc = (ny << 7) + (wn << 5) + (nf << 3) + (lane4 << 1);
        const float bb0 = __ldg(bp + nc),     bb1 = __ldg(bp + nc + 1);
        const float bb2 = __ldg(bp + nc + 2), bb3 = __ldg(bp + nc + 3);
        const int ch = nc >> 2;
#pragma unroll
        for (int mf = 0; mf < 2; ++mf) {
#pragma unroll
            for (int rh = 0; rh < 2; ++rh) {
                float v0 = acc[mf][nf][rh * 2 + 0];
                float v1 = acc[mf][nf][rh * 2 + 1];
                float p0 = __shfl_xor_sync(0xffffffffu, v0, 1);
                float p1 = __shfl_xor_sync(0xffffffffu, v1, 1);
                if (!(lane & 1)) {
                    const float zi = v0 + bb0, zf = v1 + bb1, zo = p0 + bb2, zg = p1 + bb3;
                    const float gi = 1.0f / (1.0f + expf(-zi));
                    const float gf = 1.0f / (1.0f + expf(-zf));
                    const float go = 1.0f / (1.0f + expf(-zo));
                    const float gg = tanhf(zg);
                    const int pixm = pix0 + (wm << 5) + (mf << 4) + (lane >> 2) + (rh << 3);
                    const int sidx = ((((b << 7) + ch)) << 10) + pixm;
                    const float cn = gf * c_st[sidx] + gi * gg;
                    c_st[sidx] = cn;
                    const float hn = go * tanhf(cn);
                    const float hr = f2tf32(hn);
                    const int py = (pixm >> 5) + 1, px = (pixm & 31) + 1;
                    if (layer == 1) {
                        const int o1 = ((b << 7) + ch) * 34 + py;
                        const int o2 = ((b << 8) + ch) * 34 + py;
                        const size_t p1b = (size_t)(par ^ 1) * H1P;
                        const size_t p2b = (size_t)par * L2P;
#pragma unroll
                        for (int c = 0; c < 3; ++c) if (px - c >= 0) {
                            g_padH1[p1b + (size_t)c * H1C + o1 * 36 + px - c] = hr;
                            g_padL2[p2b + (size_t)c * L2C + o2 * 36 + px - c] = hr;
                        }
                    } else if (layer == 2) {
                        const int o2 = ((b << 8) + 128 + ch) * 34 + py;
                        const int o3 = ((b << 8) + ch) * 34 + py;
                        const size_t p2b = (size_t)(par ^ 1) * L2P;
                        const size_t p3b = (size_t)par * L2P;
#pragma unroll
                        for (int c = 0; c < 3; ++c) if (px - c >= 0) {
                            g_padL2[p2b + (size_t)c * L2C + o2 * 36 + px - c] = hr;
                            g_padL3[p3b + (size_t)c * L2C + o3 * 36 + px - c] = hr;
                        }
                    } else {
                        const int o3 = ((b << 8) + 128 + ch) * 34 + py;
                        const size_t p3b = (size_t)(par ^ 1) * L2P;
#pragma unroll
                        for (int c = 0; c < 3; ++c) if (px - c >= 0)
                            g_padL3[p3b + (size_t)c * L2C + o3 * 36 + px - c] = hr;
                        h_out[sidx] = hn;
                    }
                }
            }
        }
    }
}

// ---------------- launch ----------------
extern "C" void kernel_launch(void* const* d_in, const int* in_sizes, int n_in,
                              void* d_out, int out_size) {
    const float* x1 = (const float*)d_in[0];
    const float* x2 = (const float*)d_in[1];
    const float* W1 = (const float*)d_in[2];
    const float* b1 = (const float*)d_in[3];
    const float* W2 = (const float*)d_in[4];
    const float* b2 = (const float*)d_in[5];
    const float* W3 = (const float*)d_in[6];
    const float* b3 = (const float*)d_in[7];
    float* out = (float*)d_out;

    float *p_c1, *p_c2, *p_c3, *p_wf1, *p_wf2, *p_wf3, *p_bp1, *p_bp2, *p_bp3;
    cudaGetSymbolAddress((void**)&p_c1, g_c1);
    cudaGetSymbolAddress((void**)&p_c2, g_c2);
    cudaGetSymbolAddress((void**)&p_c3, g_c3);
    cudaGetSymbolAddress((void**)&p_wf1, g_wf1);
    cudaGetSymbolAddress((void**)&p_wf2, g_wf2);
    cudaGetSymbolAddress((void**)&p_wf3, g_wf3);
    cudaGetSymbolAddress((void**)&p_bp1, g_bp1);
    cudaGetSymbolAddress((void**)&p_bp2, g_bp2);
    cudaGetSymbolAddress((void**)&p_bp3, g_bp3);

    cudaFuncSetAttribute(gemm_lstm_kernel,
                         cudaFuncAttributeMaxDynamicSharedMemorySize, SMEM_DYN);

    const dim3 ggrid(64, 4);
    const int initBlocks = (int)((INIT_TOTAL + 255) / 256);

    init_kernel<<<initBlocks, 256>>>();
    wprep_kernel<<<(K1 * 512 + 255) / 256, 256>>>(W1, b1, W2, b2, W3, b3);

    for (int t = 0; t < TT; ++t) {
        const int par = t & 1;
        pack_x_kernel<<<(BATCH * 256 * NPIX + 255) / 256, 256>>>(x1, x2, t);
        gemm_lstm_kernel<<<ggrid, 256, SMEM_DYN>>>(p_wf1, p_bp1, p_c1, nullptr,
                                                   CIN1, NCH1, 1, par);
        gemm_lstm_kernel<<<ggrid, 256, SMEM_DYN>>>(p_wf2, p_bp2, p_c2, nullptr,
                                                   CIN23, NCH23, 2, par);
        gemm_lstm_kernel<<<ggrid, 256, SMEM_DYN>>>(p_wf3, p_bp3, p_c3, out,
                                                   CIN23, NCH23, 3, par);
    }
}